// round 7
// baseline (speedup 1.0000x reference)
#include <cuda_runtime.h>

// Problem constants (fixed by the reference).
#define NN 100000
#define DD 64
#define NROW4 16            // float4s per 64-float row
#define NE 1600000
#define NB 98               // ceil(NN / 1024) scan blocks
#define NE_PAD (NE + 4 * NN) // max padded adjacency entries (2,000,000)

// Chebyshev coefficients for lambda_max = 2.0 (constant-fold: C1A=-1, C1B=0,
// C2A=-2, C2B=0).
#define C1A (-2.0f / 2.0f)
#define C1B (2.0f / 2.0f - 1.0f)
#define C2A (-4.0f / 2.0f)
#define C2B (4.0f / 2.0f - 2.0f)

typedef unsigned long long ull;

// Scratch (device globals: no allocation allowed in kernel_launch).
__device__ int    g_degi  [NN];
__device__ int    g_bsum  [128];        // per-scan-block padded sums (NB used)
__device__ int    g_boff  [128];        // exclusive scan of g_bsum
__device__ int    g_rowptr[NN + 1];     // padded starts (multiples of 4)
__device__ int    g_cursor[NN];
__device__ __align__(16) ull g_adjw[NE_PAD];  // packed (src:int32, norm:float32)
__device__ float  g_norm  [NN];
__device__ float4 g_h0    [NN * NROW4]; // aggregation sums, pass 1
__device__ float4 g_h1    [NN * NROW4]; // aggregation sums, pass 2 (x C1A)

// ---------------------------------------------------------------------------
// f32x2 packed-FMA helpers (Blackwell)
// ---------------------------------------------------------------------------
__device__ __forceinline__ ull pack2(float v) {
    ull r;
    asm("mov.b64 %0, {%1, %1};" : "=l"(r) : "f"(v));
    return r;
}
__device__ __forceinline__ void fma2(ull& d, ull a, ull b) {
    asm("fma.rn.f32x2 %0, %1, %2, %0;" : "+l"(d) : "l"(a), "l"(b));
}
__device__ __forceinline__ float2 unpack2(ull v) {
    float2 r;
    asm("mov.b64 {%0, %1}, %2;" : "=f"(r.x), "=f"(r.y) : "l"(v));
    return r;
}

// ---------------------------------------------------------------------------
// 1) degree histogram (int): deg[dst] += 1
// ---------------------------------------------------------------------------
__global__ void deg_kernel(const int4* __restrict__ dst4) {
    int t = blockIdx.x * blockDim.x + threadIdx.x;
    if (t < NE / 4) {
        int4 d = __ldg(dst4 + t);
        atomicAdd(&g_degi[d.x], 1);
        atomicAdd(&g_degi[d.y], 1);
        atomicAdd(&g_degi[d.z], 1);
        atomicAdd(&g_degi[d.w], 1);
    }
}

// ---------------------------------------------------------------------------
// 2a) per-block PADDED degree sums (1024 elements/block, shuffle reduction)
// ---------------------------------------------------------------------------
__global__ __launch_bounds__(1024) void blocksum_kernel() {
    __shared__ int wsum[32];
    int tid = threadIdx.x, lane = tid & 31, wid = tid >> 5;
    int i = blockIdx.x * 1024 + tid;
    int v = (i < NN) ? ((g_degi[i] + 3) & ~3) : 0;
#pragma unroll
    for (int off = 16; off > 0; off >>= 1)
        v += __shfl_down_sync(~0u, v, off);
    if (lane == 0) wsum[wid] = v;
    __syncthreads();
    if (wid == 0) {
        int w = wsum[lane];
#pragma unroll
        for (int off = 16; off > 0; off >>= 1)
            w += __shfl_down_sync(~0u, w, off);
        if (lane == 0) g_bsum[blockIdx.x] = w;
    }
}

// ---------------------------------------------------------------------------
// 2b) exclusive scan of the NB block sums (one block, shuffle scan)
// ---------------------------------------------------------------------------
__global__ __launch_bounds__(128) void scanbsum_kernel() {
    __shared__ int wtot[4];
    int tid = threadIdx.x, lane = tid & 31, wid = tid >> 5;
    int v = (tid < NB) ? g_bsum[tid] : 0;
    int x = v;
#pragma unroll
    for (int off = 1; off < 32; off <<= 1) {
        int y = __shfl_up_sync(~0u, x, off);
        if (lane >= off) x += y;
    }
    if (lane == 31) wtot[wid] = x;
    __syncthreads();
    int add = 0;
    for (int w = 0; w < wid; w++) add += wtot[w];
    g_boff[tid] = add + x - v;   // exclusive
}

// ---------------------------------------------------------------------------
// 2c) per-block exclusive scan (padded degs) -> row_ptr, cursor; also norm.
// ---------------------------------------------------------------------------
__global__ __launch_bounds__(1024) void scanblock_kernel() {
    __shared__ int wsum[32];
    int tid = threadIdx.x, lane = tid & 31, wid = tid >> 5;
    int i = blockIdx.x * 1024 + tid;
    int deg = (i < NN) ? g_degi[i] : 0;
    int v = (deg + 3) & ~3;
    if (i >= NN) v = 0;
    int x = v;
#pragma unroll
    for (int off = 1; off < 32; off <<= 1) {
        int y = __shfl_up_sync(~0u, x, off);
        if (lane >= off) x += y;
    }
    if (lane == 31) wsum[wid] = x;
    __syncthreads();
    if (wid == 0) {
        int w = wsum[lane];
#pragma unroll
        for (int off = 1; off < 32; off <<= 1) {
            int y = __shfl_up_sync(~0u, w, off);
            if (lane >= off) w += y;
        }
        wsum[lane] = w;
    }
    __syncthreads();
    int warpoff = (wid > 0) ? wsum[wid - 1] : 0;
    if (i < NN) {
        int ex = g_boff[blockIdx.x] + warpoff + x - v;
        g_rowptr[i] = ex;
        g_cursor[i] = ex;
        g_norm[i]   = rsqrtf(fmaxf((float)deg, 1.0f));
        if (i == NN - 1) g_rowptr[NN] = ex + v;
    }
}

// ---------------------------------------------------------------------------
// 3) CSR fill: adjw[cursor[dst]++] = (src, norm[src])
// ---------------------------------------------------------------------------
__global__ void fill_kernel(const int4* __restrict__ src4,
                            const int4* __restrict__ dst4) {
    int t = blockIdx.x * blockDim.x + threadIdx.x;
    if (t < NE / 4) {
        int4 s = __ldg(src4 + t);
        int4 d = __ldg(dst4 + t);
        float n0 = g_norm[s.x], n1 = g_norm[s.y], n2 = g_norm[s.z], n3 = g_norm[s.w];
        g_adjw[atomicAdd(&g_cursor[d.x], 1)] =
            (ull)(unsigned)s.x | ((ull)__float_as_uint(n0) << 32);
        g_adjw[atomicAdd(&g_cursor[d.y], 1)] =
            (ull)(unsigned)s.y | ((ull)__float_as_uint(n1) << 32);
        g_adjw[atomicAdd(&g_cursor[d.z], 1)] =
            (ull)(unsigned)s.z | ((ull)__float_as_uint(n2) << 32);
        g_adjw[atomicAdd(&g_cursor[d.w], 1)] =
            (ull)(unsigned)s.w | ((ull)__float_as_uint(n3) << 32);
    }
}

// ---------------------------------------------------------------------------
// 4) gather passes. 16 threads per node; each thread owns one float4 chunk.
//    List read as aligned int4 (2 packed edges each). Pads have w=0 -> no-op.
//    PASS 0: h0[i]    = sum norm[s]  * feat[s]
//    PASS 1: h1[i] = C1A * sum norm2[s] * h0[s]   (norm2 = w*w)
// ---------------------------------------------------------------------------
template <int PASS>
__global__ __launch_bounds__(256) void gather_kernel(const float4* __restrict__ feat4) {
    int t = blockIdx.x * blockDim.x + threadIdx.x;
    if (t >= NN * NROW4) return;
    int i = t >> 4;
    int c = t & 15;

    int j   = g_rowptr[i];       // multiple of 4
    int end = g_rowptr[i + 1];   // multiple of 4
    const int4* __restrict__ aw4 = reinterpret_cast<const int4*>(g_adjw);
    const float4* __restrict__ srcbuf =
        (PASS == 0) ? feat4 : reinterpret_cast<const float4*>(g_h0);

    float4 a = make_float4(0.f, 0.f, 0.f, 0.f);
    float4 b = make_float4(0.f, 0.f, 0.f, 0.f);

#define EDGE_FMA(ACC, S, WF)                                            \
    {                                                                   \
        float4 v = __ldg(srcbuf + ((S) << 4) + c);                      \
        float ww = (PASS == 0) ? (WF) : (WF) * (WF);                    \
        ACC.x = fmaf(ww, v.x, ACC.x);                                   \
        ACC.y = fmaf(ww, v.y, ACC.y);                                   \
        ACC.z = fmaf(ww, v.z, ACC.z);                                   \
        ACC.w = fmaf(ww, v.w, ACC.w);                                   \
    }

    // 8 edges per iter: 4 list int4s + 8 feat4 loads in flight.
    for (; j + 8 <= end; j += 8) {
        int h = j >> 1;
        int4 p0 = aw4[h], p1 = aw4[h + 1], p2 = aw4[h + 2], p3 = aw4[h + 3];
        EDGE_FMA(a, p0.x, __int_as_float(p0.y));
        EDGE_FMA(b, p0.z, __int_as_float(p0.w));
        EDGE_FMA(a, p1.x, __int_as_float(p1.y));
        EDGE_FMA(b, p1.z, __int_as_float(p1.w));
        EDGE_FMA(a, p2.x, __int_as_float(p2.y));
        EDGE_FMA(b, p2.z, __int_as_float(p2.w));
        EDGE_FMA(a, p3.x, __int_as_float(p3.y));
        EDGE_FMA(b, p3.z, __int_as_float(p3.w));
    }
    if (j < end) {   // exactly 4 remaining (end - j is a multiple of 4)
        int h = j >> 1;
        int4 p0 = aw4[h], p1 = aw4[h + 1];
        EDGE_FMA(a, p0.x, __int_as_float(p0.y));
        EDGE_FMA(b, p0.z, __int_as_float(p0.w));
        EDGE_FMA(a, p1.x, __int_as_float(p1.y));
        EDGE_FMA(b, p1.z, __int_as_float(p1.w));
    }
#undef EDGE_FMA

    float4 r;
    if (PASS == 0) {
        r.x = a.x + b.x; r.y = a.y + b.y; r.z = a.z + b.z; r.w = a.w + b.w;
        g_h0[t] = r;
    } else {
        r.x = C1A * (a.x + b.x);
        r.y = C1A * (a.y + b.y);
        r.z = C1A * (a.z + b.z);
        r.w = C1A * (a.w + b.w);
        g_h1[t] = r;
    }
}

// ---------------------------------------------------------------------------
// 5) fused epilogue GEMM:
//    t0 = feat;  t1 = c1a*n*h0 + c1b*t0;  t2 = c2a*n*h1 + c2b*t1 - t0
//    out = t0@W0 + t1@W1 + t2@W2 + bias
//    256 threads = 4 col-groups (16 cols, warp-uniform) x 64 row-groups
//    (4 rows each). W (48KB) in shared; packed f32x2 accumulators.
// ---------------------------------------------------------------------------
__global__ __launch_bounds__(256) void final_kernel(
    const float4* __restrict__ feat4,
    const float4* __restrict__ W4,
    const float4* __restrict__ bias4,
    float4* __restrict__ out4) {
    __shared__ __align__(16) float Ws[3 * 64 * 64];   // 49152 B
    {
        float4* Ws4 = reinterpret_cast<float4*>(Ws);
        for (int i = threadIdx.x; i < 3 * 64 * 16; i += 256)
            Ws4[i] = __ldg(W4 + i);
    }
    __syncthreads();

    const int cg   = threadIdx.x >> 6;
    const int rg   = threadIdx.x & 63;
    const int base = blockIdx.x * 256;

    int   rows[4];
    bool  valid[4];
    float n[4];
#pragma unroll
    for (int r = 0; r < 4; r++) {
        int row  = base + rg + 64 * r;
        valid[r] = row < NN;
        rows[r]  = valid[r] ? row : 0;
        n[r]     = g_norm[rows[r]];
    }

    ull acc[4][8];
#pragma unroll
    for (int r = 0; r < 4; r++)
#pragma unroll
        for (int cp = 0; cp < 8; cp++) acc[r][cp] = 0ULL;

    const ulonglong2* Wp = reinterpret_cast<const ulonglong2*>(Ws);

    for (int dc = 0; dc < 16; dc++) {
        float4 a0[4], a1[4], a2[4];
#pragma unroll
        for (int r = 0; r < 4; r++) {
            int b = (rows[r] << 4) + dc;
            a0[r] = __ldg(feat4 + b);
            a1[r] = g_h0[b];
            a2[r] = g_h1[b];
        }
#pragma unroll
        for (int s = 0; s < 4; s++) {
            const int d = dc * 4 + s;
            ull tt[3][4];
#pragma unroll
            for (int r = 0; r < 4; r++) {
                float t0  = reinterpret_cast<const float*>(&a0[r])[s];
                float h0v = reinterpret_cast<const float*>(&a1[r])[s];
                float h1v = reinterpret_cast<const float*>(&a2[r])[s];
                float t1 = fmaf(C1A * n[r], h0v, C1B * t0);
                float t2 = fmaf(C2A * n[r], h1v, fmaf(C2B, t1, -t0));
                tt[0][r] = pack2(t0);
                tt[1][r] = pack2(t1);
                tt[2][r] = pack2(t2);
            }
#pragma unroll
            for (int k = 0; k < 3; k++) {
                const ulonglong2* p = Wp + (k * 1024 + d * 16 + cg * 4);
                ull w[8];
#pragma unroll
                for (int j = 0; j < 4; j++) {
                    ulonglong2 v = p[j];       // LDS.128, warp-uniform broadcast
                    w[2 * j]     = v.x;
                    w[2 * j + 1] = v.y;
                }
#pragma unroll
                for (int r = 0; r < 4; r++)
#pragma unroll
                    for (int cp = 0; cp < 8; cp++)
                        fma2(acc[r][cp], tt[k][r], w[cp]);
            }
        }
    }

    float4 b4[4];
#pragma unroll
    for (int j = 0; j < 4; j++) b4[j] = __ldg(bias4 + cg * 4 + j);
#pragma unroll
    for (int r = 0; r < 4; r++) {
        if (!valid[r]) continue;
#pragma unroll
        for (int j = 0; j < 4; j++) {
            float2 lo = unpack2(acc[r][2 * j]);
            float2 hi = unpack2(acc[r][2 * j + 1]);
            float4 o;
            o.x = lo.x + b4[j].x;
            o.y = lo.y + b4[j].y;
            o.z = hi.x + b4[j].z;
            o.w = hi.y + b4[j].w;
            out4[(rows[r] << 4) + cg * 4 + j] = o;
        }
    }
}

// ---------------------------------------------------------------------------
// launch (graph-capturable: only async memsets + kernel launches)
// ---------------------------------------------------------------------------
extern "C" void kernel_launch(void* const* d_in, const int* in_sizes, int n_in,
                              void* d_out, int out_size) {
    const float* feat = (const float*)d_in[0];
    const float* W    = (const float*)d_in[1];
    const float* bias = (const float*)d_in[2];
    const int*   esrc = (const int*)d_in[3];
    const int*   edst = (const int*)d_in[4];
    float*       out  = (float*)d_out;

    void *p_degi = nullptr, *p_adjw = nullptr;
    cudaGetSymbolAddress(&p_degi, g_degi);
    cudaGetSymbolAddress(&p_adjw, g_adjw);
    cudaMemsetAsync(p_degi, 0, NN * sizeof(int));
    cudaMemsetAsync(p_adjw, 0, (size_t)NE_PAD * sizeof(ull));  // zero pads

    const int T = 256;

    deg_kernel<<<(NE / 4 + T - 1) / T, T>>>((const int4*)edst);
    blocksum_kernel<<<NB, 1024>>>();
    scanbsum_kernel<<<1, 128>>>();
    scanblock_kernel<<<NB, 1024>>>();
    fill_kernel<<<(NE / 4 + T - 1) / T, T>>>((const int4*)esrc, (const int4*)edst);

    gather_kernel<0><<<(NN * NROW4 + T - 1) / T, T>>>((const float4*)feat);
    gather_kernel<1><<<(NN * NROW4 + T - 1) / T, T>>>((const float4*)feat);

    final_kernel<<<(NN + 255) / 256, 256>>>((const float4*)feat,
                                            (const float4*)W,
                                            (const float4*)bias,
                                            (float4*)out);
}